// round 1
// baseline (speedup 1.0000x reference)
#include <cuda_runtime.h>

#define DIM 128
#define NROWS 2048
#define BT 128
#define DK 16

typedef unsigned long long ull;

// d-major scratch: A[d][n] = hi, C[d][m] = hj + b1
__device__ __align__(128) float g_At[DIM * NROWS];
__device__ __align__(128) float g_Ct[DIM * NROWS];

// ---------------------------------------------------------------------------
// Precompute: side 0 -> At[d][n] = sum_k z_i[n,k]*W1[k,d]
//             side 1 -> Ct[d][m] = sum_k z_j[m,k]*W1[128+k,d] + b1[d]
// grid (64, 2), block 256. Each block: 32 rows x 128 d. Thread: 2 rows x 8 d.
// ---------------------------------------------------------------------------
__global__ void precompute_kernel(const float* __restrict__ z_i,
                                  const float* __restrict__ z_j,
                                  const float* __restrict__ W1,
                                  const float* __restrict__ b1) {
    __shared__ __align__(16) float Zs[32][DIM];   // 16KB
    __shared__ __align__(16) float W1s[32][DIM];  // 16KB (k-chunk)

    const int side = blockIdx.y;
    const float* z  = (side == 0) ? z_i : z_j;
    const float* w1 = W1 + side * DIM * DIM;
    const int rowBase = blockIdx.x * 32;
    const int tid = threadIdx.x;

    // load Zs (32 rows x 128): 1024 float4 / 256 threads
    #pragma unroll
    for (int l = 0; l < 4; l++) {
        int idx = tid + 256 * l;
        int r = idx >> 5, c4 = idx & 31;
        float4 v = ((const float4*)(z + (size_t)(rowBase + r) * DIM))[c4];
        *(float4*)&Zs[r][c4 * 4] = v;
    }

    const int dg = (tid & 15) * 8;   // 8 d-outputs
    const int ng = (tid >> 4) * 2;   // 2 rows

    float acc[2][8];
    #pragma unroll
    for (int i = 0; i < 2; i++)
        #pragma unroll
        for (int j = 0; j < 8; j++) acc[i][j] = 0.f;

    for (int k0 = 0; k0 < DIM; k0 += 32) {
        __syncthreads();
        #pragma unroll
        for (int l = 0; l < 4; l++) {
            int idx = tid + 256 * l;
            int r = idx >> 5, c4 = idx & 31;
            float4 v = ((const float4*)(w1 + (size_t)(k0 + r) * DIM))[c4];
            *(float4*)&W1s[r][c4 * 4] = v;
        }
        __syncthreads();
        #pragma unroll
        for (int kk = 0; kk < 32; kk++) {
            float4 wa = *(const float4*)&W1s[kk][dg];
            float4 wb = *(const float4*)&W1s[kk][dg + 4];
            float w[8] = {wa.x, wa.y, wa.z, wa.w, wb.x, wb.y, wb.z, wb.w};
            #pragma unroll
            for (int i = 0; i < 2; i++) {
                float zv = Zs[ng + i][k0 + kk];
                #pragma unroll
                for (int j = 0; j < 8; j++) acc[i][j] = fmaf(zv, w[j], acc[i][j]);
            }
        }
    }

    float* dst = (side == 0) ? g_At : g_Ct;
    #pragma unroll
    for (int j = 0; j < 8; j++) {
        float bb = (side == 0) ? 0.f : b1[dg + j];
        #pragma unroll
        for (int i = 0; i < 2; i++)
            dst[(size_t)(dg + j) * NROWS + rowBase + ng + i] = acc[i][j] + bb;
    }
}

// ---------------------------------------------------------------------------
// Main: out[n,m] = sum_d relu(A[d][n] + C[d][m]) * w2[d] + b2
// grid (16,16), block 256 (16x16), thread tile 8 rows x 8 cols.
// f32x2 packed add/fma; relu via 2x scalar FMNMX (alu pipe).
// A stored duplicated in smem so the broadcast operand packs for free.
// ---------------------------------------------------------------------------
__global__ void __launch_bounds__(256, 2)
mlp_score_kernel(const float* __restrict__ W2, const float* __restrict__ b2p,
                 float* __restrict__ out) {
    __shared__ __align__(16) float As[DK][2 * BT];  // dup pairs {a,a}: 16KB
    __shared__ __align__(16) float Cs[DK][BT];      // 8KB
    __shared__ __align__(8)  float Ws[DK][2];       // dup {w,w}

    const int tid = threadIdx.x;
    const int tc = tid & 15;        // col group (8 cols)
    const int tr = tid >> 4;        // row group (8 rows)
    const int rowBase = blockIdx.y * BT;
    const int colBase = blockIdx.x * BT;

    ull acc[8][4];
    #pragma unroll
    for (int i = 0; i < 8; i++)
        #pragma unroll
        for (int j = 0; j < 4; j++) acc[i][j] = 0ull;

    for (int d0 = 0; d0 < DIM; d0 += DK) {
        __syncthreads();
        // stage A (duplicated) and C chunks: DK x BT each
        #pragma unroll
        for (int l = 0; l < 2; l++) {
            int idx = tid + 256 * l;             // 0..511
            int d = idx >> 5, r4 = idx & 31;     // 32 float4 per 128-row
            float4 v = *(const float4*)&g_At[(size_t)(d0 + d) * NROWS + rowBase + r4 * 4];
            *(float4*)&As[d][8 * r4]     = make_float4(v.x, v.x, v.y, v.y);
            *(float4*)&As[d][8 * r4 + 4] = make_float4(v.z, v.z, v.w, v.w);
        }
        #pragma unroll
        for (int l = 0; l < 2; l++) {
            int idx = tid + 256 * l;
            int d = idx >> 5, r4 = idx & 31;
            float4 v = *(const float4*)&g_Ct[(size_t)(d0 + d) * NROWS + colBase + r4 * 4];
            *(float4*)&Cs[d][4 * r4] = v;
        }
        if (tid < DK) {
            float w = W2[d0 + tid];
            Ws[tid][0] = w; Ws[tid][1] = w;
        }
        __syncthreads();

        #pragma unroll 4
        for (int d = 0; d < DK; d++) {
            ull w2 = *(const ull*)&Ws[d][0];
            ull a2[8], c2[4];
            {
                const ulonglong2* ap = (const ulonglong2*)&As[d][16 * tr];
                ulonglong2 v0 = ap[0], v1 = ap[1], v2 = ap[2], v3 = ap[3];
                a2[0] = v0.x; a2[1] = v0.y; a2[2] = v1.x; a2[3] = v1.y;
                a2[4] = v2.x; a2[5] = v2.y; a2[6] = v3.x; a2[7] = v3.y;
                const ulonglong2* cp = (const ulonglong2*)&Cs[d][8 * tc];
                ulonglong2 u0 = cp[0], u1 = cp[1];
                c2[0] = u0.x; c2[1] = u0.y; c2[2] = u1.x; c2[3] = u1.y;
            }
            #pragma unroll
            for (int i = 0; i < 8; i++) {
                #pragma unroll
                for (int j = 0; j < 4; j++) {
                    ull t, r;
                    asm("add.rn.f32x2 %0, %1, %2;" : "=l"(t) : "l"(a2[i]), "l"(c2[j]));
                    float lo, hi;
                    asm("mov.b64 {%0, %1}, %2;" : "=f"(lo), "=f"(hi) : "l"(t));
                    lo = fmaxf(lo, 0.f);
                    hi = fmaxf(hi, 0.f);
                    asm("mov.b64 %0, {%1, %2};" : "=l"(r) : "f"(lo), "f"(hi));
                    asm("fma.rn.f32x2 %0, %1, %2, %3;"
                        : "=l"(acc[i][j]) : "l"(r), "l"(w2), "l"(acc[i][j]));
                }
            }
        }
    }

    const float b2 = *b2p;
    #pragma unroll
    for (int i = 0; i < 8; i++) {
        float o[8];
        #pragma unroll
        for (int j = 0; j < 4; j++) {
            float lo, hi;
            asm("mov.b64 {%0, %1}, %2;" : "=f"(lo), "=f"(hi) : "l"(acc[i][j]));
            o[2 * j]     = lo + b2;
            o[2 * j + 1] = hi + b2;
        }
        float* dst = &out[(size_t)(rowBase + tr * 8 + i) * NROWS + colBase + tc * 8];
        *(float4*)dst       = make_float4(o[0], o[1], o[2], o[3]);
        *(float4*)(dst + 4) = make_float4(o[4], o[5], o[6], o[7]);
    }
}

// ---------------------------------------------------------------------------
extern "C" void kernel_launch(void* const* d_in, const int* in_sizes, int n_in,
                              void* d_out, int out_size) {
    (void)in_sizes; (void)n_in; (void)out_size;
    const float* z_i = (const float*)d_in[0];
    const float* z_j = (const float*)d_in[1];
    const float* W1  = (const float*)d_in[2];
    const float* b1  = (const float*)d_in[3];
    const float* W2  = (const float*)d_in[4];
    const float* b2  = (const float*)d_in[5];
    float* out = (float*)d_out;

    precompute_kernel<<<dim3(64, 2), 256>>>(z_i, z_j, W1, b1);
    mlp_score_kernel<<<dim3(16, 16), 256>>>(W2, b2, out);
}

// round 3
// speedup vs baseline: 1.0666x; 1.0666x over previous
#include <cuda_runtime.h>

#define DIM 128
#define NROWS 2048
#define BT 128
#define DK 16
#define NCHUNK (DIM / DK)

typedef unsigned long long ull;

// d-major scratch: A[d][n] = hi, C[d][m] = hj + b1
__device__ __align__(128) float g_At[DIM * NROWS];
__device__ __align__(128) float g_Ct[DIM * NROWS];

// ---------------------------------------------------------------------------
// Precompute: side 0 -> At[d][n] = sum_k z_i[n,k]*W1[k,d]
//             side 1 -> Ct[d][m] = sum_k z_j[m,k]*W1[128+k,d] + b1[d]
// ---------------------------------------------------------------------------
__global__ void precompute_kernel(const float* __restrict__ z_i,
                                  const float* __restrict__ z_j,
                                  const float* __restrict__ W1,
                                  const float* __restrict__ b1) {
    __shared__ __align__(16) float Zs[32][DIM];
    __shared__ __align__(16) float W1s[32][DIM];

    const int side = blockIdx.y;
    const float* z  = (side == 0) ? z_i : z_j;
    const float* w1 = W1 + side * DIM * DIM;
    const int rowBase = blockIdx.x * 32;
    const int tid = threadIdx.x;

    #pragma unroll
    for (int l = 0; l < 4; l++) {
        int idx = tid + 256 * l;
        int r = idx >> 5, c4 = idx & 31;
        float4 v = ((const float4*)(z + (size_t)(rowBase + r) * DIM))[c4];
        *(float4*)&Zs[r][c4 * 4] = v;
    }

    const int dg = (tid & 15) * 8;
    const int ng = (tid >> 4) * 2;

    float acc[2][8];
    #pragma unroll
    for (int i = 0; i < 2; i++)
        #pragma unroll
        for (int j = 0; j < 8; j++) acc[i][j] = 0.f;

    for (int k0 = 0; k0 < DIM; k0 += 32) {
        __syncthreads();
        #pragma unroll
        for (int l = 0; l < 4; l++) {
            int idx = tid + 256 * l;
            int r = idx >> 5, c4 = idx & 31;
            float4 v = ((const float4*)(w1 + (size_t)(k0 + r) * DIM))[c4];
            *(float4*)&W1s[r][c4 * 4] = v;
        }
        __syncthreads();
        #pragma unroll
        for (int kk = 0; kk < 32; kk++) {
            float4 wa = *(const float4*)&W1s[kk][dg];
            float4 wb = *(const float4*)&W1s[kk][dg + 4];
            float w[8] = {wa.x, wa.y, wa.z, wa.w, wb.x, wb.y, wb.z, wb.w};
            #pragma unroll
            for (int i = 0; i < 2; i++) {
                float zv = Zs[ng + i][k0 + kk];
                #pragma unroll
                for (int j = 0; j < 8; j++) acc[i][j] = fmaf(zv, w[j], acc[i][j]);
            }
        }
    }

    float* dst = (side == 0) ? g_At : g_Ct;
    #pragma unroll
    for (int j = 0; j < 8; j++) {
        float bb = (side == 0) ? 0.f : b1[dg + j];
        #pragma unroll
        for (int i = 0; i < 2; i++)
            dst[(size_t)(dg + j) * NROWS + rowBase + ng + i] = acc[i][j] + bb;
    }
}

// ---------------------------------------------------------------------------
// Main: out[n,m] = sum_d relu(A[d][n] + C[d][m]) * w2[d] + b2
// Double-buffered smem (register staging). Per output pair:
//   add.f32x2 (fma pipe) + 2x FMNMX (alu pipe) + fma.f32x2 (fma pipe).
// ---------------------------------------------------------------------------
__global__ void __launch_bounds__(256, 2)
mlp_score_kernel(const float* __restrict__ W2, const float* __restrict__ b2p,
                 float* __restrict__ out) {
    // 2 x (16 x 256) dup-A = 32KB ; 2 x (16 x 128) C = 16KB ; total 48KB
    __shared__ __align__(16) float As[2][DK][2 * BT];
    __shared__ __align__(16) float Cs[2][DK][BT];

    const int tid = threadIdx.x;
    const int tc = tid & 15;        // col group (4 pairs = 8 cols)
    const int tr = tid >> 4;        // row group (8 rows)
    const int rowBase = blockIdx.y * BT;
    const int colBase = blockIdx.x * BT;

    // staging index decomposition (same for A and C, 2 float4 each)
    const int sd0 = tid >> 5;              // d for l=0   (0..7)
    const int sd1 = sd0 + 8;               // d for l=1   (8..15)
    const int sr4 = tid & 31;              // float4 index within 128-row

    const float b2 = __ldg(b2p);
    ull binit;
    asm("mov.b64 %0, {%1, %1};" : "=l"(binit) : "f"(b2));

    ull acc[8][4];
    #pragma unroll
    for (int i = 0; i < 8; i++)
        #pragma unroll
        for (int j = 0; j < 4; j++) acc[i][j] = binit;

    // ---- stage chunk 0 into buffer 0 ----
    {
        float4 a0 = *(const float4*)&g_At[(size_t)sd0 * NROWS + rowBase + sr4 * 4];
        float4 a1 = *(const float4*)&g_At[(size_t)sd1 * NROWS + rowBase + sr4 * 4];
        float4 c0 = *(const float4*)&g_Ct[(size_t)sd0 * NROWS + colBase + sr4 * 4];
        float4 c1 = *(const float4*)&g_Ct[(size_t)sd1 * NROWS + colBase + sr4 * 4];
        *(float4*)&As[0][sd0][8 * sr4]     = make_float4(a0.x, a0.x, a0.y, a0.y);
        *(float4*)&As[0][sd0][8 * sr4 + 4] = make_float4(a0.z, a0.z, a0.w, a0.w);
        *(float4*)&As[0][sd1][8 * sr4]     = make_float4(a1.x, a1.x, a1.y, a1.y);
        *(float4*)&As[0][sd1][8 * sr4 + 4] = make_float4(a1.z, a1.z, a1.w, a1.w);
        *(float4*)&Cs[0][sd0][4 * sr4] = c0;
        *(float4*)&Cs[0][sd1][4 * sr4] = c1;
    }
    __syncthreads();

    for (int c = 0; c < NCHUNK; c++) {
        const int buf = c & 1;
        const int nbuf = buf ^ 1;

        // ---- prefetch next chunk into registers (overlaps with compute) ----
        float4 a0, a1, c0, c1;
        if (c + 1 < NCHUNK) {
            const size_t dnext = (size_t)(c + 1) * DK;
            a0 = *(const float4*)&g_At[(dnext + sd0) * NROWS + rowBase + sr4 * 4];
            a1 = *(const float4*)&g_At[(dnext + sd1) * NROWS + rowBase + sr4 * 4];
            c0 = *(const float4*)&g_Ct[(dnext + sd0) * NROWS + colBase + sr4 * 4];
            c1 = *(const float4*)&g_Ct[(dnext + sd1) * NROWS + colBase + sr4 * 4];
        }

        // ---- compute on current buffer ----
        #pragma unroll 4
        for (int d = 0; d < DK; d++) {
            float w = __ldg(W2 + c * DK + d);
            ull w2;
            asm("mov.b64 %0, {%1, %1};" : "=l"(w2) : "f"(w));

            ull a2[8], c2[4];
            {
                const ulonglong2* ap = (const ulonglong2*)&As[buf][d][16 * tr];
                ulonglong2 v0 = ap[0], v1 = ap[1], v2 = ap[2], v3 = ap[3];
                a2[0] = v0.x; a2[1] = v0.y; a2[2] = v1.x; a2[3] = v1.y;
                a2[4] = v2.x; a2[5] = v2.y; a2[6] = v3.x; a2[7] = v3.y;
                const ulonglong2* cp = (const ulonglong2*)&Cs[buf][d][8 * tc];
                ulonglong2 u0 = cp[0], u1 = cp[1];
                c2[0] = u0.x; c2[1] = u0.y; c2[2] = u1.x; c2[3] = u1.y;
            }
            #pragma unroll
            for (int i = 0; i < 8; i++) {
                #pragma unroll
                for (int j = 0; j < 4; j++) {
                    ull t, r;
                    asm("add.rn.f32x2 %0, %1, %2;"
                        : "=l"(t) : "l"(a2[i]), "l"(c2[j]));
                    float lo, hi;
                    asm("mov.b64 {%0, %1}, %2;" : "=f"(lo), "=f"(hi) : "l"(t));
                    lo = fmaxf(lo, 0.f);
                    hi = fmaxf(hi, 0.f);
                    asm("mov.b64 %0, {%1, %2};" : "=l"(r) : "f"(lo), "f"(hi));
                    asm("fma.rn.f32x2 %0, %1, %2, %0;"
                        : "+l"(acc[i][j]) : "l"(r), "l"(w2));
                }
            }
        }

        // ---- write staged registers into the other buffer ----
        if (c + 1 < NCHUNK) {
            *(float4*)&As[nbuf][sd0][8 * sr4]     = make_float4(a0.x, a0.x, a0.y, a0.y);
            *(float4*)&As[nbuf][sd0][8 * sr4 + 4] = make_float4(a0.z, a0.z, a0.w, a0.w);
            *(float4*)&As[nbuf][sd1][8 * sr4]     = make_float4(a1.x, a1.x, a1.y, a1.y);
            *(float4*)&As[nbuf][sd1][8 * sr4 + 4] = make_float4(a1.z, a1.z, a1.w, a1.w);
            *(float4*)&Cs[nbuf][sd0][4 * sr4] = c0;
            *(float4*)&Cs[nbuf][sd1][4 * sr4] = c1;
        }
        __syncthreads();
    }

    // ---- epilogue: b2 already folded into acc init ----
    #pragma unroll
    for (int i = 0; i < 8; i++) {
        float* dst = &out[(size_t)(rowBase + tr * 8 + i) * NROWS + colBase + tc * 8];
        *(ulonglong2*)dst       = make_ulonglong2(acc[i][0], acc[i][1]);
        *(ulonglong2*)(dst + 4) = make_ulonglong2(acc[i][2], acc[i][3]);
    }
}

// ---------------------------------------------------------------------------
extern "C" void kernel_launch(void* const* d_in, const int* in_sizes, int n_in,
                              void* d_out, int out_size) {
    (void)in_sizes; (void)n_in; (void)out_size;
    const float* z_i = (const float*)d_in[0];
    const float* z_j = (const float*)d_in[1];
    const float* W1  = (const float*)d_in[2];
    const float* b1  = (const float*)d_in[3];
    const float* W2  = (const float*)d_in[4];
    const float* b2  = (const float*)d_in[5];
    float* out = (float*)d_out;

    precompute_kernel<<<dim3(64, 2), 256>>>(z_i, z_j, W1, b1);
    mlp_score_kernel<<<dim3(16, 16), 256>>>(W2, b2, out);
}